// round 3
// baseline (speedup 1.0000x reference)
#include <cuda_runtime.h>

#define BATCH_MAX 16384
#define XDIM 64
#define ADIM 16
#define NCON 8
#define N_ITERS 250
#define POW_ITERS 32
#define EPSC 0.05f   /* 1/(2*PEN) */

// ---------------- scratch (static device globals; no runtime alloc) ----------------
__device__ float g_Y [BATCH_MAX * 512];   // Qc_m x  (flattened r = m*64+i)
__device__ float g_S [BATCH_MAX * 64];    // S = 0.5 Lg Lg^T  (8x8)
__device__ float g_q [BATCH_MAX * 16];    // dual linear term (bottom half zeros)
__device__ float g_Lg[BATCH_MAX * 128];   // Lg_h (8x16)

// =====================================================================
// Kernel 1: Y[b][r] = sum_k X[b][k] * W[r][k],  W = Qc flattened [512][64]
// Tiled SGEMM, M=batch, N=512, K=64. Tile 128x128, 8x8 micro, 256 thr.
// =====================================================================
#define K1_SMEM ((128 * 68 + 64 * 132) * 4)

__global__ __launch_bounds__(256) void k1_gemm(const float* __restrict__ X,
                                               const float* __restrict__ W)
{
    extern __shared__ float sm[];
    float (*As)[68]  = (float(*)[68])sm;               // [m][k] padded
    float (*Bs)[132] = (float(*)[132])(sm + 128 * 68); // [k][n] padded (transposed)

    const int tid = threadIdx.x;
    const int m0 = blockIdx.y * 128;
    const int n0 = blockIdx.x * 128;

    {
        int row  = tid & 127;
        int half = tid >> 7;
        #pragma unroll
        for (int it = 0; it < 8; it++) {
            int kq = half + it * 2;  // 0..15
            float4 xv = *(const float4*)(X + (size_t)(m0 + row) * 64 + kq * 4);
            *(float4*)(&As[row][kq * 4]) = xv;
            float4 wv = *(const float4*)(W + (size_t)(n0 + row) * 64 + kq * 4);
            Bs[kq * 4 + 0][row] = wv.x;
            Bs[kq * 4 + 1][row] = wv.y;
            Bs[kq * 4 + 2][row] = wv.z;
            Bs[kq * 4 + 3][row] = wv.w;
        }
    }
    __syncthreads();

    const int tx = tid & 15, ty = tid >> 4;   // 8x8 micro: rows ty*8, cols tx*8
    float c[8][8] = {};
    #pragma unroll
    for (int kq = 0; kq < 16; kq++) {
        float a[8][4];
        float bb[4][8];
        #pragma unroll
        for (int i = 0; i < 8; i++) {
            float4 t = *(const float4*)(&As[ty * 8 + i][kq * 4]);
            a[i][0] = t.x; a[i][1] = t.y; a[i][2] = t.z; a[i][3] = t.w;
        }
        #pragma unroll
        for (int u = 0; u < 4; u++) {
            float4 t0 = *(const float4*)(&Bs[kq * 4 + u][tx * 8]);
            float4 t1 = *(const float4*)(&Bs[kq * 4 + u][tx * 8 + 4]);
            bb[u][0] = t0.x; bb[u][1] = t0.y; bb[u][2] = t0.z; bb[u][3] = t0.w;
            bb[u][4] = t1.x; bb[u][5] = t1.y; bb[u][6] = t1.z; bb[u][7] = t1.w;
        }
        #pragma unroll
        for (int u = 0; u < 4; u++)
            #pragma unroll
            for (int i = 0; i < 8; i++)
                #pragma unroll
                for (int j = 0; j < 8; j++)
                    c[i][j] = fmaf(a[i][u], bb[u][j], c[i][j]);
    }
    #pragma unroll
    for (int i = 0; i < 8; i++) {
        float* orow = g_Y + (size_t)(m0 + ty * 8 + i) * 512 + n0 + tx * 8;
        *(float4*)(orow)     = make_float4(c[i][0], c[i][1], c[i][2], c[i][3]);
        *(float4*)(orow + 4) = make_float4(c[i][4], c[i][5], c[i][6], c[i][7]);
    }
}

// =====================================================================
// Kernel 2: per-element setup.  Warp per element, 4 elements / 128-thr block.
// Produces S, q, Lg.  A loads fully coalesced (512B/instr) + shfl reduce.
// =====================================================================
#define GS_STRIDE 68   // padded row stride for gradc to kill bank conflicts

__global__ __launch_bounds__(128) void k2_setup(
    const float* __restrict__ Xg, const float* __restrict__ Ag,
    const float* __restrict__ Bg, const float* __restrict__ ccg,
    const float* __restrict__ dcg, const float* __restrict__ adg)
{
    __shared__ float xs [4][64];
    __shared__ float zs [4][64];
    __shared__ float gsm[4][NCON * GS_STRIDE];  // gradc = Qc x + cc
    __shared__ float Bsm[4][1024];              // B tile [64][16]
    __shared__ float Lgs[4][128];               // Lg (8x16)
    __shared__ float ccs[512];

    const int tid = threadIdx.x;
    const int w = tid >> 5, lane = tid & 31;
    const int b = blockIdx.x * 4 + w;

    for (int idx = tid; idx < 512; idx += 128) ccs[idx] = ccg[idx];

    if (lane < 16)
        *(float4*)&xs[w][lane * 4] = *(const float4*)(Xg + (size_t)b * 64 + lane * 4);

    {
        const float* Bb = Bg + (size_t)b * 1024;
        #pragma unroll
        for (int it = 0; it < 8; it++) {
            int idx = it * 128 + lane * 4;
            *(float4*)&Bsm[w][idx] = *(const float4*)(Bb + idx);
        }
    }
    __syncthreads();

    // z = A x  — coalesced: float4 index p = it*32+lane over the whole 64x64 tile.
    // Row r = p>>4 (each it covers rows it*2 + {0,1}); reduce within half-warps.
    {
        const float4* A4 = (const float4*)(Ag + (size_t)b * 4096);
        #pragma unroll
        for (int it = 0; it < 32; it++) {
            int p  = it * 32 + lane;
            int c4 = p & 15;
            float4 a4 = A4[p];
            float4 xv = *(const float4*)(&xs[w][c4 * 4]);
            float part = fmaf(a4.x, xv.x, a4.y * xv.y);
            part = fmaf(a4.z, xv.z, part);
            part = fmaf(a4.w, xv.w, part);
            part += __shfl_xor_sync(0xffffffffu, part, 1);
            part += __shfl_xor_sync(0xffffffffu, part, 2);
            part += __shfl_xor_sync(0xffffffffu, part, 4);
            part += __shfl_xor_sync(0xffffffffu, part, 8);
            if ((lane & 15) == 0)
                zs[w][it * 2 + (lane >> 4)] = part;
        }
    }
    __syncwarp();

    // gradc = Y + cc  (store with padded stride)
    {
        const float* Yb = g_Y + (size_t)b * 512;
        #pragma unroll
        for (int it = 0; it < 4; it++) {
            int idx = it * 128 + lane * 4;
            int m = idx >> 6, i = idx & 63;
            float4 yv = *(const float4*)(Yb + idx);
            yv.x += ccs[idx + 0]; yv.y += ccs[idx + 1];
            yv.z += ccs[idx + 2]; yv.w += ccs[idx + 3];
            *(float4*)&gsm[w][m * GS_STRIDE + i] = yv;
        }
    }
    __syncwarp();

    // dots: sa = x·gradc, sb = x·cc, sc = z·gradc  per constraint
    float sa[NCON], sb[NCON], sc[NCON];
    {
        int i1 = lane, i2 = lane + 32;
        float x1 = xs[w][i1], x2 = xs[w][i2];
        float z1 = zs[w][i1], z2 = zs[w][i2];
        #pragma unroll
        for (int m = 0; m < NCON; m++) {
            float ga = gsm[w][m * GS_STRIDE + i1], gb2 = gsm[w][m * GS_STRIDE + i2];
            float ca = ccs[m * 64 + i1], cb = ccs[m * 64 + i2];
            sa[m] = fmaf(x2, gb2, x1 * ga);
            sb[m] = fmaf(x2, cb, x1 * ca);
            sc[m] = fmaf(z2, gb2, z1 * ga);
        }
    }
    #pragma unroll
    for (int off = 16; off; off >>= 1) {
        #pragma unroll
        for (int m = 0; m < NCON; m++) {
            sa[m] += __shfl_xor_sync(0xffffffffu, sa[m], off);
            sb[m] += __shfl_xor_sync(0xffffffffu, sb[m], off);
            sc[m] += __shfl_xor_sync(0xffffffffu, sc[m], off);
        }
    }

    // Lg[m][a] = -sum_i gradc[m][i] * B[i][a]   (lane: m = lane>>2, a-quad = lane&3)
    {
        int m = lane >> 2, aq = lane & 3;
        float4 acc = make_float4(0.f, 0.f, 0.f, 0.f);
        const float4* B4 = (const float4*)&Bsm[w][0];
        #pragma unroll
        for (int i = 0; i < 64; i++) {
            float gv = gsm[w][m * GS_STRIDE + i];
            float4 bv = B4[i * 4 + aq];
            acc.x = fmaf(gv, bv.x, acc.x);
            acc.y = fmaf(gv, bv.y, acc.y);
            acc.z = fmaf(gv, bv.z, acc.z);
            acc.w = fmaf(gv, bv.w, acc.w);
        }
        acc.x = -acc.x; acc.y = -acc.y; acc.z = -acc.z; acc.w = -acc.w;
        *(float4*)&Lgs[w][m * 16 + aq * 4] = acc;
        *(float4*)(g_Lg + (size_t)b * 128 + m * 16 + aq * 4) = acc;
    }
    __syncwarp();

    // q (top = bvec - Lg a_des, bottom = 0)
    if (lane < NCON) {
        int m = lane;
        float g    = 0.5f * sa[m] + 0.5f * sb[m] - dcg[m];  // g = 0.5 x·y + x·cc - dc
        float bvec = sc[m] + g;                             // = -Lf_h - h
        float qm = bvec;
        const float* ad = adg + (size_t)b * 16;
        #pragma unroll
        for (int a = 0; a < 16; a++) qm = fmaf(-Lgs[w][m * 16 + a], ad[a], qm);
        g_q[(size_t)b * 16 + m] = qm;
        g_q[(size_t)b * 16 + 8 + m] = 0.f;
    }

    // S = 0.5 Lg Lg^T  (64 entries, 2 per lane)
    #pragma unroll
    for (int e = 0; e < 2; e++) {
        int idx = lane + e * 32;
        int r = idx >> 3, cI = idx & 7;
        float s = 0.f;
        #pragma unroll
        for (int a = 0; a < 16; a++) s = fmaf(Lgs[w][r * 16 + a], Lgs[w][cI * 16 + a], s);
        g_S[(size_t)b * 64 + idx] = 0.5f * s;
    }
}

// =====================================================================
// Kernel 3: thread per element.  Power iteration (8x8) -> lambda_max of M
// via closed form, then 250 FISTA iterations, then primal recovery.
// =====================================================================
__global__ __launch_bounds__(128) void k3_fista(const float* __restrict__ adg,
                                                float* __restrict__ out, int batch)
{
    int b = blockIdx.x * 128 + threadIdx.x;
    if (b >= batch) return;

    float S[64];
    {
        const float4* S4 = (const float4*)(g_S + (size_t)b * 64);
        #pragma unroll
        for (int i = 0; i < 16; i++) {
            float4 v = S4[i];
            S[i * 4 + 0] = v.x; S[i * 4 + 1] = v.y; S[i * 4 + 2] = v.z; S[i * 4 + 3] = v.w;
        }
    }
    float q[16];
    {
        const float4* q4 = (const float4*)(g_q + (size_t)b * 16);
        #pragma unroll
        for (int i = 0; i < 4; i++) {
            float4 v = q4[i];
            q[i * 4 + 0] = v.x; q[i * 4 + 1] = v.y; q[i * 4 + 2] = v.z; q[i * 4 + 3] = v.w;
        }
    }

    // ---- power iteration on S (8x8) ----
    float v[8];
    #pragma unroll
    for (int k = 0; k < 8; k++) v[k] = 1.0f + 0.0625f * (float)k;
    #pragma unroll 1
    for (int it = 0; it < POW_ITERS; it++) {
        float wv[8];
        #pragma unroll
        for (int k = 0; k < 8; k++) {
            float acc = 0.f;
            #pragma unroll
            for (int j = 0; j < 8; j++) acc = fmaf(S[k * 8 + j], v[j], acc);
            wv[k] = acc;
        }
        float ss = 1e-30f;
        #pragma unroll
        for (int k = 0; k < 8; k++) ss = fmaf(wv[k], wv[k], ss);
        float inv = rsqrtf(ss);
        #pragma unroll
        for (int k = 0; k < 8; k++) v[k] = wv[k] * inv;
    }
    float num = 0.f, den = 1e-30f;
    #pragma unroll
    for (int k = 0; k < 8; k++) {
        float acc = 0.f;
        #pragma unroll
        for (int j = 0; j < 8; j++) acc = fmaf(S[k * 8 + j], v[j], acc);
        num = fmaf(v[k], acc, num);
        den = fmaf(v[k], v[k], den);
    }
    float mu = fmaxf(num / den, 0.f);
    // lambda_max(M) = eps + (mu + sqrt(mu^2 + 4 eps^2)) / 2
    float lamMax = EPSC + 0.5f * (mu + sqrtf(fmaf(mu, mu, 4.f * EPSC * EPSC)));
    float L = lamMax * 1.005f + 1e-6f;  // inflation covers power-iter underestimate
    float t = 1.0f / L;

    // ---- FISTA ----
    float lam[16], y[16];
    #pragma unroll
    for (int k = 0; k < 16; k++) { lam[k] = 0.f; y[k] = 0.f; }
    float tk = 1.0f;
    #pragma unroll 1
    for (int it = 0; it < N_ITERS; it++) {
        float wv[8];
        #pragma unroll
        for (int k = 0; k < 8; k++) {
            float acc = 0.f;
            #pragma unroll
            for (int j = 0; j < 8; j++) acc = fmaf(S[k * 8 + j], y[j], acc);
            wv[k] = acc;
        }
        float tk1 = 0.5f * (1.0f + sqrtf(fmaf(4.0f * tk, tk, 1.0f)));
        float beta = (tk - 1.0f) / tk1;
        #pragma unroll
        for (int k = 0; k < 8; k++) {
            float e  = EPSC * (y[k] + y[k + 8]);
            float gt = wv[k] + e - q[k];
            float gb = e - q[k + 8];
            float lt = fmaxf(fmaf(-t, gt, y[k]), 0.f);
            float lb = fmaxf(fmaf(-t, gb, y[k + 8]), 0.f);
            y[k]     = fmaf(beta, lt - lam[k], lt);
            y[k + 8] = fmaf(beta, lb - lam[k + 8], lb);
            lam[k] = lt; lam[k + 8] = lb;
        }
        tk = tk1;
    }

    // ---- primal recovery: a = a_des + 0.5 Lg^T lam_top ----
    float a[16];
    {
        const float4* ad4 = (const float4*)(adg + (size_t)b * 16);
        #pragma unroll
        for (int i = 0; i < 4; i++) {
            float4 t4 = ad4[i];
            a[i * 4 + 0] = t4.x; a[i * 4 + 1] = t4.y; a[i * 4 + 2] = t4.z; a[i * 4 + 3] = t4.w;
        }
        const float* Lgb = g_Lg + (size_t)b * 128;
        #pragma unroll
        for (int m = 0; m < 8; m++) {
            float lm = 0.5f * lam[m];
            #pragma unroll
            for (int j = 0; j < 16; j++) a[j] = fmaf(lm, Lgb[m * 16 + j], a[j]);
        }
    }
    float4* o4 = (float4*)(out + (size_t)b * 16);
    #pragma unroll
    for (int i = 0; i < 4; i++)
        o4[i] = make_float4(a[i * 4 + 0], a[i * 4 + 1], a[i * 4 + 2], a[i * 4 + 3]);
}

// =====================================================================
extern "C" void kernel_launch(void* const* d_in, const int* in_sizes, int n_in,
                              void* d_out, int out_size)
{
    const float* a_des = (const float*)d_in[0];
    const float* x     = (const float*)d_in[1];
    const float* A     = (const float*)d_in[2];
    const float* B     = (const float*)d_in[3];
    const float* Qc    = (const float*)d_in[4];
    const float* cc    = (const float*)d_in[5];
    const float* dc    = (const float*)d_in[6];
    const int batch = in_sizes[0] / ADIM;   // 16384

    // No static guard (harness forbids them). Host-side attribute set is
    // capture-safe (not a stream op) and idempotent.
    cudaFuncSetAttribute(k1_gemm, cudaFuncAttributeMaxDynamicSharedMemorySize, K1_SMEM);

    dim3 g1(512 / 128, batch / 128);
    k1_gemm<<<g1, 256, K1_SMEM>>>(x, Qc);
    k2_setup<<<batch / 4, 128>>>(x, A, B, cc, dc, a_des);
    k3_fista<<<(batch + 127) / 128, 128>>>(a_des, (float*)d_out, batch);
}

// round 4
// speedup vs baseline: 1.4337x; 1.4337x over previous
#include <cuda_runtime.h>

#define BATCH_MAX 16384
#define XDIM 64
#define ADIM 16
#define NCON 8
#define N_ITERS 250
#define POW_ITERS 32
#define EPSC 0.05f   /* 1/(2*PEN) */

// ---------------- scratch (static device globals; no runtime alloc) ----------------
__device__ float g_Y [BATCH_MAX * 512];   // Qc_m x  (flattened r = m*64+i)
__device__ float g_S [BATCH_MAX * 64];    // S = 0.5 Lg Lg^T  (8x8)
__device__ float g_q [BATCH_MAX * 16];    // dual linear term (bottom half zeros)
__device__ float g_Lg[BATCH_MAX * 128];   // Lg_h (8x16)

// =====================================================================
// Kernel 1: Y[b][r] = sum_k X[b][k] * W[r][k],  W = Qc flattened [512][64]
// Tiled SGEMM, M=batch, N=512, K=64.  Block 256 threads, 64x64 tile.
// (Proven R1 config: 57 regs, occ 46%, 44us.)
// =====================================================================
__global__ __launch_bounds__(256) void k1_gemm(const float* __restrict__ X,
                                               const float* __restrict__ W)
{
    __shared__ float As[64][72];   // [m][k] padded
    __shared__ float Bs[64][72];   // [k][n] padded (transposed on load)
    const int tid = threadIdx.x;
    const int m0 = blockIdx.y * 64;
    const int n0 = blockIdx.x * 64;

    {
        int row = tid & 63;
        int kq0 = tid >> 6;  // 0..3
        #pragma unroll
        for (int it = 0; it < 4; it++) {
            int kq = kq0 + it * 4;  // 0..15
            float4 xv = *(const float4*)(X + (size_t)(m0 + row) * 64 + kq * 4);
            *(float4*)(&As[row][kq * 4]) = xv;
            float4 wv = *(const float4*)(W + (size_t)(n0 + row) * 64 + kq * 4);
            Bs[kq * 4 + 0][row] = wv.x;
            Bs[kq * 4 + 1][row] = wv.y;
            Bs[kq * 4 + 2][row] = wv.z;
            Bs[kq * 4 + 3][row] = wv.w;
        }
    }
    __syncthreads();

    const int tx = tid & 15, ty = tid >> 4;
    float c[4][4] = {};
    #pragma unroll
    for (int kq = 0; kq < 16; kq++) {
        float a[4][4], bb[4][4];
        #pragma unroll
        for (int i = 0; i < 4; i++) {
            float4 t = *(const float4*)(&As[ty * 4 + i][kq * 4]);
            a[i][0] = t.x; a[i][1] = t.y; a[i][2] = t.z; a[i][3] = t.w;
        }
        #pragma unroll
        for (int u = 0; u < 4; u++) {
            float4 t = *(const float4*)(&Bs[kq * 4 + u][tx * 4]);
            bb[u][0] = t.x; bb[u][1] = t.y; bb[u][2] = t.z; bb[u][3] = t.w;
        }
        #pragma unroll
        for (int i = 0; i < 4; i++)
            #pragma unroll
            for (int j = 0; j < 4; j++) {
                c[i][j] = fmaf(a[i][0], bb[0][j], c[i][j]);
                c[i][j] = fmaf(a[i][1], bb[1][j], c[i][j]);
                c[i][j] = fmaf(a[i][2], bb[2][j], c[i][j]);
                c[i][j] = fmaf(a[i][3], bb[3][j], c[i][j]);
            }
    }
    #pragma unroll
    for (int i = 0; i < 4; i++) {
        float4 o = make_float4(c[i][0], c[i][1], c[i][2], c[i][3]);
        *(float4*)(g_Y + (size_t)(m0 + ty * 4 + i) * 512 + n0 + tx * 4) = o;
    }
}

// =====================================================================
// Kernel 2: per-element setup.  Warp per element, 4 elements / 128-thr block.
// z=Ax chunked through smem: coalesced LDG (128 wavefronts/element = floor),
// conflict-free LDS phases (stride 68 + r=lane&7/seg=lane>>3 mapping), 2
// shfls/chunk.  Staging buffer aliases the gradc buffer (same shape).
// =====================================================================
#define GS_STRIDE 68

__global__ __launch_bounds__(128) void k2_setup(
    const float* __restrict__ Xg, const float* __restrict__ Ag,
    const float* __restrict__ Bg, const float* __restrict__ ccg,
    const float* __restrict__ dcg, const float* __restrict__ adg)
{
    __shared__ float xs [4][64];
    __shared__ float zs [4][64];
    __shared__ float gsm[4][NCON * GS_STRIDE];  // aliased: A-stage, then gradc
    __shared__ float Bsm[4][1024];              // B tile [64][16]
    __shared__ float Lgs[4][128];               // Lg (8x16)
    __shared__ float ccs[512];

    const int tid = threadIdx.x;
    const int w = tid >> 5, lane = tid & 31;
    const int b = blockIdx.x * 4 + w;

    for (int idx = tid; idx < 512; idx += 128) ccs[idx] = ccg[idx];

    if (lane < 16)
        *(float4*)&xs[w][lane * 4] = *(const float4*)(Xg + (size_t)b * 64 + lane * 4);

    {
        const float* Bb = Bg + (size_t)b * 1024;
        #pragma unroll
        for (int it = 0; it < 8; it++) {
            int idx = it * 128 + lane * 4;
            *(float4*)&Bsm[w][idx] = *(const float4*)(Bb + idx);
        }
    }
    __syncthreads();

    // ---- z = A x, chunked: 8 rows/chunk, 8 chunks ----
    {
        const float4* A4 = (const float4*)(Ag + (size_t)b * 4096);
        const int r   = lane & 7;    // row within chunk
        const int seg = lane >> 3;   // 16-float segment within row
        #pragma unroll
        for (int ch = 0; ch < 8; ch++) {
            // coalesced load: 128 consecutive float4 (8 rows) -> staged @ stride 68
            #pragma unroll
            for (int j = 0; j < 4; j++) {
                int p = j * 32 + lane;          // float4 idx within chunk
                float4 v = A4[ch * 128 + p];
                int row = p >> 4, c4 = p & 15;
                *(float4*)&gsm[w][row * GS_STRIDE + c4 * 4] = v;
            }
            __syncwarp();
            float acc = 0.f;
            #pragma unroll
            for (int j = 0; j < 4; j++) {
                float4 av = *(const float4*)&gsm[w][r * GS_STRIDE + seg * 16 + j * 4];
                float4 xv = *(const float4*)&xs[w][seg * 16 + j * 4];
                acc = fmaf(av.x, xv.x, acc);
                acc = fmaf(av.y, xv.y, acc);
                acc = fmaf(av.z, xv.z, acc);
                acc = fmaf(av.w, xv.w, acc);
            }
            acc += __shfl_xor_sync(0xffffffffu, acc, 8);
            acc += __shfl_xor_sync(0xffffffffu, acc, 16);
            if (seg == 0) zs[w][ch * 8 + r] = acc;
            __syncwarp();
        }
    }

    // ---- gradc = Y + cc  (reuse gsm buffer, stride GS_STRIDE) ----
    {
        const float* Yb = g_Y + (size_t)b * 512;
        #pragma unroll
        for (int it = 0; it < 4; it++) {
            int idx = it * 128 + lane * 4;
            int m = idx >> 6, i = idx & 63;
            float4 yv = *(const float4*)(Yb + idx);
            yv.x += ccs[idx + 0]; yv.y += ccs[idx + 1];
            yv.z += ccs[idx + 2]; yv.w += ccs[idx + 3];
            *(float4*)&gsm[w][m * GS_STRIDE + i] = yv;
        }
    }
    __syncwarp();

    // dots: sa = x·gradc, sb = x·cc, sc = z·gradc  per constraint
    float sa[NCON], sb[NCON], sc[NCON];
    {
        int i1 = lane, i2 = lane + 32;
        float x1 = xs[w][i1], x2 = xs[w][i2];
        float z1 = zs[w][i1], z2 = zs[w][i2];
        #pragma unroll
        for (int m = 0; m < NCON; m++) {
            float ga = gsm[w][m * GS_STRIDE + i1], gb2 = gsm[w][m * GS_STRIDE + i2];
            float ca = ccs[m * 64 + i1], cb = ccs[m * 64 + i2];
            sa[m] = fmaf(x2, gb2, x1 * ga);
            sb[m] = fmaf(x2, cb, x1 * ca);
            sc[m] = fmaf(z2, gb2, z1 * ga);
        }
    }
    #pragma unroll
    for (int off = 16; off; off >>= 1) {
        #pragma unroll
        for (int m = 0; m < NCON; m++) {
            sa[m] += __shfl_xor_sync(0xffffffffu, sa[m], off);
            sb[m] += __shfl_xor_sync(0xffffffffu, sb[m], off);
            sc[m] += __shfl_xor_sync(0xffffffffu, sc[m], off);
        }
    }

    // Lg[m][a] = -sum_i gradc[m][i] * B[i][a]
    {
        int m = lane >> 2, aq = lane & 3;
        float4 acc = make_float4(0.f, 0.f, 0.f, 0.f);
        const float4* B4 = (const float4*)&Bsm[w][0];
        #pragma unroll
        for (int i = 0; i < 64; i++) {
            float gv = gsm[w][m * GS_STRIDE + i];
            float4 bv = B4[i * 4 + aq];
            acc.x = fmaf(gv, bv.x, acc.x);
            acc.y = fmaf(gv, bv.y, acc.y);
            acc.z = fmaf(gv, bv.z, acc.z);
            acc.w = fmaf(gv, bv.w, acc.w);
        }
        acc.x = -acc.x; acc.y = -acc.y; acc.z = -acc.z; acc.w = -acc.w;
        *(float4*)&Lgs[w][m * 16 + aq * 4] = acc;
        *(float4*)(g_Lg + (size_t)b * 128 + m * 16 + aq * 4) = acc;
    }
    __syncwarp();

    // q (top = bvec - Lg a_des, bottom = 0)
    if (lane < NCON) {
        int m = lane;
        float g    = 0.5f * sa[m] + 0.5f * sb[m] - dcg[m];
        float bvec = sc[m] + g;
        float qm = bvec;
        const float* ad = adg + (size_t)b * 16;
        #pragma unroll
        for (int a = 0; a < 16; a++) qm = fmaf(-Lgs[w][m * 16 + a], ad[a], qm);
        g_q[(size_t)b * 16 + m] = qm;
        g_q[(size_t)b * 16 + 8 + m] = 0.f;
    }

    // S = 0.5 Lg Lg^T
    #pragma unroll
    for (int e = 0; e < 2; e++) {
        int idx = lane + e * 32;
        int r = idx >> 3, cI = idx & 7;
        float s = 0.f;
        #pragma unroll
        for (int a = 0; a < 16; a++) s = fmaf(Lgs[w][r * 16 + a], Lgs[w][cI * 16 + a], s);
        g_S[(size_t)b * 64 + idx] = 0.5f * s;
    }
}

// =====================================================================
// Kernel 3: thread per element.  Power iteration (32 it) -> lambda_max,
// 250 FISTA iterations, primal recovery.
// =====================================================================
__global__ __launch_bounds__(128) void k3_fista(const float* __restrict__ adg,
                                                float* __restrict__ out, int batch)
{
    int b = blockIdx.x * 128 + threadIdx.x;
    if (b >= batch) return;

    float S[64];
    {
        const float4* S4 = (const float4*)(g_S + (size_t)b * 64);
        #pragma unroll
        for (int i = 0; i < 16; i++) {
            float4 v = S4[i];
            S[i * 4 + 0] = v.x; S[i * 4 + 1] = v.y; S[i * 4 + 2] = v.z; S[i * 4 + 3] = v.w;
        }
    }
    float q[16];
    {
        const float4* q4 = (const float4*)(g_q + (size_t)b * 16);
        #pragma unroll
        for (int i = 0; i < 4; i++) {
            float4 v = q4[i];
            q[i * 4 + 0] = v.x; q[i * 4 + 1] = v.y; q[i * 4 + 2] = v.z; q[i * 4 + 3] = v.w;
        }
    }

    // ---- power iteration on S (8x8) ----
    float v[8];
    #pragma unroll
    for (int k = 0; k < 8; k++) v[k] = 1.0f + 0.0625f * (float)k;
    #pragma unroll 1
    for (int it = 0; it < POW_ITERS; it++) {
        float wv[8];
        #pragma unroll
        for (int k = 0; k < 8; k++) {
            float acc = 0.f;
            #pragma unroll
            for (int j = 0; j < 8; j++) acc = fmaf(S[k * 8 + j], v[j], acc);
            wv[k] = acc;
        }
        float ss = 1e-30f;
        #pragma unroll
        for (int k = 0; k < 8; k++) ss = fmaf(wv[k], wv[k], ss);
        float inv = rsqrtf(ss);
        #pragma unroll
        for (int k = 0; k < 8; k++) v[k] = wv[k] * inv;
    }
    float num = 0.f, den = 1e-30f;
    #pragma unroll
    for (int k = 0; k < 8; k++) {
        float acc = 0.f;
        #pragma unroll
        for (int j = 0; j < 8; j++) acc = fmaf(S[k * 8 + j], v[j], acc);
        num = fmaf(v[k], acc, num);
        den = fmaf(v[k], v[k], den);
    }
    float mu = fmaxf(num / den, 0.f);
    float lamMax = EPSC + 0.5f * (mu + sqrtf(fmaf(mu, mu, 4.f * EPSC * EPSC)));
    float L = lamMax * 1.005f + 1e-6f;
    float t = 1.0f / L;

    // ---- FISTA ----
    float lam[16], y[16];
    #pragma unroll
    for (int k = 0; k < 16; k++) { lam[k] = 0.f; y[k] = 0.f; }
    float tk = 1.0f;
    #pragma unroll 1
    for (int it = 0; it < N_ITERS; it++) {
        float wv[8];
        #pragma unroll
        for (int k = 0; k < 8; k++) {
            float acc = 0.f;
            #pragma unroll
            for (int j = 0; j < 8; j++) acc = fmaf(S[k * 8 + j], y[j], acc);
            wv[k] = acc;
        }
        float tk1 = 0.5f * (1.0f + sqrtf(fmaf(4.0f * tk, tk, 1.0f)));
        float beta = (tk - 1.0f) / tk1;
        #pragma unroll
        for (int k = 0; k < 8; k++) {
            float e  = EPSC * (y[k] + y[k + 8]);
            float gt = wv[k] + e - q[k];
            float gb = e - q[k + 8];
            float lt = fmaxf(fmaf(-t, gt, y[k]), 0.f);
            float lb = fmaxf(fmaf(-t, gb, y[k + 8]), 0.f);
            y[k]     = fmaf(beta, lt - lam[k], lt);
            y[k + 8] = fmaf(beta, lb - lam[k + 8], lb);
            lam[k] = lt; lam[k + 8] = lb;
        }
        tk = tk1;
    }

    // ---- primal recovery: a = a_des + 0.5 Lg^T lam_top ----
    float a[16];
    {
        const float4* ad4 = (const float4*)(adg + (size_t)b * 16);
        #pragma unroll
        for (int i = 0; i < 4; i++) {
            float4 t4 = ad4[i];
            a[i * 4 + 0] = t4.x; a[i * 4 + 1] = t4.y; a[i * 4 + 2] = t4.z; a[i * 4 + 3] = t4.w;
        }
        const float* Lgb = g_Lg + (size_t)b * 128;
        #pragma unroll
        for (int m = 0; m < 8; m++) {
            float lm = 0.5f * lam[m];
            #pragma unroll
            for (int j = 0; j < 16; j++) a[j] = fmaf(lm, Lgb[m * 16 + j], a[j]);
        }
    }
    float4* o4 = (float4*)(out + (size_t)b * 16);
    #pragma unroll
    for (int i = 0; i < 4; i++)
        o4[i] = make_float4(a[i * 4 + 0], a[i * 4 + 1], a[i * 4 + 2], a[i * 4 + 3]);
}

// =====================================================================
extern "C" void kernel_launch(void* const* d_in, const int* in_sizes, int n_in,
                              void* d_out, int out_size)
{
    const float* a_des = (const float*)d_in[0];
    const float* x     = (const float*)d_in[1];
    const float* A     = (const float*)d_in[2];
    const float* B     = (const float*)d_in[3];
    const float* Qc    = (const float*)d_in[4];
    const float* cc    = (const float*)d_in[5];
    const float* dc    = (const float*)d_in[6];
    const int batch = in_sizes[0] / ADIM;   // 16384

    dim3 g1(512 / 64, batch / 64);
    k1_gemm<<<g1, 256>>>(x, Qc);
    k2_setup<<<batch / 4, 128>>>(x, A, B, cc, dc, a_des);
    k3_fista<<<(batch + 127) / 128, 128>>>(a_des, (float*)d_out, batch);
}

// round 5
// speedup vs baseline: 1.6423x; 1.1455x over previous
#include <cuda_runtime.h>

#define BATCH_MAX 16384
#define XDIM 64
#define ADIM 16
#define NCON 8
#define N_ITERS 140
#define POW_ITERS 32
#define EPSC 0.05f   /* 1/(2*PEN) */

typedef unsigned long long ull;

// ---------------- packed f32x2 helpers (sm_103a FFMA2) ----------------
__device__ __forceinline__ ull ffma2(ull a, ull b, ull c) {
    ull d;
    asm("fma.rn.f32x2 %0, %1, %2, %3;" : "=l"(d) : "l"(a), "l"(b), "l"(c));
    return d;
}
__device__ __forceinline__ float hadd2(ull p) {
    unsigned lo, hi;
    asm("mov.b64 {%0, %1}, %2;" : "=r"(lo), "=r"(hi) : "l"(p));
    return __uint_as_float(lo) + __uint_as_float(hi);
}
__device__ __forceinline__ ull pack2(float a, float b) {
    ull d;
    asm("mov.b64 %0, {%1, %2};" : "=l"(d)
        : "r"(__float_as_uint(a)), "r"(__float_as_uint(b)));
    return d;
}
// 8-dot with packed rows: Sr = 4 packed pairs, yp = 4 packed pairs
__device__ __forceinline__ float dot8p(const ull* Sr, const ull* yp) {
    ull acc = ffma2(Sr[0], yp[0], 0ULL);
    acc = ffma2(Sr[1], yp[1], acc);
    acc = ffma2(Sr[2], yp[2], acc);
    acc = ffma2(Sr[3], yp[3], acc);
    return hadd2(acc);
}

// ---------------- scratch (static device globals; no runtime alloc) ----------------
__device__ float g_Y [BATCH_MAX * 512];   // Qc_m x  (flattened r = m*64+i)
__device__ float g_S [BATCH_MAX * 64];    // S = 0.5 Lg Lg^T  (8x8)
__device__ float g_q [BATCH_MAX * 8];     // dual linear term (top half only; bottom == 0)
__device__ float g_Lg[BATCH_MAX * 128];   // Lg_h (8x16)

// =====================================================================
// Kernel 1: Y[b][r] = sum_k X[b][k] * W[r][k],  W = Qc flattened [512][64]
// Broadcast-W GEMM: lane = m-row; W read via uniform-address LDS.128
// (1 wavefront), k-packed FFMA2.  Block 128 thr, tile m=128 x n=64, K=64.
// =====================================================================
#define K1_XS_BYTES  (16 * 129 * 16)                 /* float4 Xs[16][129] */
#define K1_WK_BYTES  (64 * 64 * 4)                   /* float  Wk[64][64]  */
#define K1_BUF_BYTES (32 * 129 * 4)                  /* float  buf[32][129]*/
#define K1_SMEM (K1_XS_BYTES + K1_WK_BYTES + K1_BUF_BYTES)

__global__ __launch_bounds__(128) void k1_gemm(const float* __restrict__ X,
                                               const float* __restrict__ W)
{
    extern __shared__ char sm_raw[];
    float4 (*Xs4)[129] = (float4(*)[129])sm_raw;
    float  (*Wk)[64]   = (float(*)[64])(sm_raw + K1_XS_BYTES);
    float  (*buf)[129] = (float(*)[129])(sm_raw + K1_XS_BYTES + K1_WK_BYTES);

    const int t  = threadIdx.x;
    const int m0 = blockIdx.x * 128;
    const int n0 = blockIdx.y * 64;
    const int kq = t & 15, rg = t >> 4;

    const float4* X4 = (const float4*)X;
    const float4* W4 = (const float4*)W;
    #pragma unroll
    for (int it = 0; it < 16; it++) {
        int row = it * 8 + rg;
        Xs4[kq][row] = X4[(size_t)(m0 + row) * 16 + kq];
    }
    #pragma unroll
    for (int it = 0; it < 8; it++) {
        int n = it * 8 + rg;
        *(float4*)&Wk[n][kq * 4] = W4[(size_t)(n0 + n) * 16 + kq];
    }
    __syncthreads();

    const int lane = t & 31, w = t >> 5;
    const int m = w * 32 + lane;

    #pragma unroll 1
    for (int pass = 0; pass < 2; pass++) {
        ull acc2[32];
        #pragma unroll
        for (int n = 0; n < 32; n++) acc2[n] = 0ULL;

        const float (*Wp)[64] = Wk + pass * 32;
        #pragma unroll 4
        for (int kq2 = 0; kq2 < 16; kq2++) {
            ulonglong2 xq = *(const ulonglong2*)&Xs4[kq2][m];
            #pragma unroll
            for (int n = 0; n < 32; n++) {
                ulonglong2 wq = *(const ulonglong2*)&Wp[n][kq2 * 4];
                acc2[n] = ffma2(wq.x, xq.x, acc2[n]);
                acc2[n] = ffma2(wq.y, xq.y, acc2[n]);
            }
        }

        #pragma unroll
        for (int n = 0; n < 32; n++) buf[n][m] = hadd2(acc2[n]);
        __syncthreads();
        {
            int n4 = t & 7, mg = t >> 3;
            #pragma unroll
            for (int s = 0; s < 8; s++) {
                int mr = s * 16 + mg;
                float4 o = make_float4(buf[n4 * 4 + 0][mr], buf[n4 * 4 + 1][mr],
                                       buf[n4 * 4 + 2][mr], buf[n4 * 4 + 3][mr]);
                ((float4*)g_Y)[(size_t)(m0 + mr) * 128 + n0 / 4 + pass * 8 + n4] = o;
            }
        }
        __syncthreads();
    }
}

// =====================================================================
// Kernel 2: per-element setup.  Warp per element, 4 elements / 128-thr block.
// z=Ax chunked through smem with register prefetch (1 chunk lookahead).
// =====================================================================
#define GS_STRIDE 68

__global__ __launch_bounds__(128) void k2_setup(
    const float* __restrict__ Xg, const float* __restrict__ Ag,
    const float* __restrict__ Bg, const float* __restrict__ ccg,
    const float* __restrict__ dcg, const float* __restrict__ adg)
{
    __shared__ float xs [4][64];
    __shared__ float zs [4][64];
    __shared__ float gsm[4][NCON * GS_STRIDE];  // aliased: A-stage, then gradc
    __shared__ float Bsm[4][1024];              // B tile [64][16]
    __shared__ float Lgs[4][128];               // Lg (8x16)
    __shared__ float ccs[512];

    const int tid = threadIdx.x;
    const int w = tid >> 5, lane = tid & 31;
    const int b = blockIdx.x * 4 + w;

    for (int idx = tid; idx < 512; idx += 128) ccs[idx] = ccg[idx];

    if (lane < 16)
        *(float4*)&xs[w][lane * 4] = *(const float4*)(Xg + (size_t)b * 64 + lane * 4);

    {
        const float* Bb = Bg + (size_t)b * 1024;
        #pragma unroll
        for (int it = 0; it < 8; it++) {
            int idx = it * 128 + lane * 4;
            *(float4*)&Bsm[w][idx] = *(const float4*)(Bb + idx);
        }
    }
    __syncthreads();

    // ---- z = A x, chunked 8 rows/chunk, register prefetch ----
    {
        const float4* A4 = (const float4*)(Ag + (size_t)b * 4096);
        const int r   = lane & 7;
        const int seg = lane >> 3;
        float4 pre[4];
        #pragma unroll
        for (int j = 0; j < 4; j++) pre[j] = A4[j * 32 + lane];
        #pragma unroll
        for (int ch = 0; ch < 8; ch++) {
            float4 cur[4];
            #pragma unroll
            for (int j = 0; j < 4; j++) cur[j] = pre[j];
            if (ch < 7) {
                #pragma unroll
                for (int j = 0; j < 4; j++) pre[j] = A4[(ch + 1) * 128 + j * 32 + lane];
            }
            #pragma unroll
            for (int j = 0; j < 4; j++) {
                int p = j * 32 + lane;
                int row = p >> 4, c4 = p & 15;
                *(float4*)&gsm[w][row * GS_STRIDE + c4 * 4] = cur[j];
            }
            __syncwarp();
            float acc = 0.f;
            #pragma unroll
            for (int j = 0; j < 4; j++) {
                float4 av = *(const float4*)&gsm[w][r * GS_STRIDE + seg * 16 + j * 4];
                float4 xv = *(const float4*)&xs[w][seg * 16 + j * 4];
                acc = fmaf(av.x, xv.x, acc);
                acc = fmaf(av.y, xv.y, acc);
                acc = fmaf(av.z, xv.z, acc);
                acc = fmaf(av.w, xv.w, acc);
            }
            acc += __shfl_xor_sync(0xffffffffu, acc, 8);
            acc += __shfl_xor_sync(0xffffffffu, acc, 16);
            if (seg == 0) zs[w][ch * 8 + r] = acc;
            __syncwarp();
        }
    }

    // ---- gradc = Y + cc ----
    {
        const float* Yb = g_Y + (size_t)b * 512;
        #pragma unroll
        for (int it = 0; it < 4; it++) {
            int idx = it * 128 + lane * 4;
            int m = idx >> 6, i = idx & 63;
            float4 yv = *(const float4*)(Yb + idx);
            yv.x += ccs[idx + 0]; yv.y += ccs[idx + 1];
            yv.z += ccs[idx + 2]; yv.w += ccs[idx + 3];
            *(float4*)&gsm[w][m * GS_STRIDE + i] = yv;
        }
    }
    __syncwarp();

    // dots: sa = x·gradc, sb = x·cc, sc = z·gradc
    float sa[NCON], sb[NCON], sc[NCON];
    {
        int i1 = lane, i2 = lane + 32;
        float x1 = xs[w][i1], x2 = xs[w][i2];
        float z1 = zs[w][i1], z2 = zs[w][i2];
        #pragma unroll
        for (int m = 0; m < NCON; m++) {
            float ga = gsm[w][m * GS_STRIDE + i1], gb2 = gsm[w][m * GS_STRIDE + i2];
            float ca = ccs[m * 64 + i1], cb = ccs[m * 64 + i2];
            sa[m] = fmaf(x2, gb2, x1 * ga);
            sb[m] = fmaf(x2, cb, x1 * ca);
            sc[m] = fmaf(z2, gb2, z1 * ga);
        }
    }
    #pragma unroll
    for (int off = 16; off; off >>= 1) {
        #pragma unroll
        for (int m = 0; m < NCON; m++) {
            sa[m] += __shfl_xor_sync(0xffffffffu, sa[m], off);
            sb[m] += __shfl_xor_sync(0xffffffffu, sb[m], off);
            sc[m] += __shfl_xor_sync(0xffffffffu, sc[m], off);
        }
    }

    // Lg[m][a] = -sum_i gradc[m][i] * B[i][a]
    {
        int m = lane >> 2, aq = lane & 3;
        float4 acc = make_float4(0.f, 0.f, 0.f, 0.f);
        const float4* B4 = (const float4*)&Bsm[w][0];
        #pragma unroll
        for (int i = 0; i < 64; i++) {
            float gv = gsm[w][m * GS_STRIDE + i];
            float4 bv = B4[i * 4 + aq];
            acc.x = fmaf(gv, bv.x, acc.x);
            acc.y = fmaf(gv, bv.y, acc.y);
            acc.z = fmaf(gv, bv.z, acc.z);
            acc.w = fmaf(gv, bv.w, acc.w);
        }
        acc.x = -acc.x; acc.y = -acc.y; acc.z = -acc.z; acc.w = -acc.w;
        *(float4*)&Lgs[w][m * 16 + aq * 4] = acc;
        *(float4*)(g_Lg + (size_t)b * 128 + m * 16 + aq * 4) = acc;
    }
    __syncwarp();

    // q top = bvec - Lg a_des   (bottom half provably zero; not stored)
    if (lane < NCON) {
        int m = lane;
        float g    = 0.5f * sa[m] + 0.5f * sb[m] - dcg[m];
        float bvec = sc[m] + g;
        float qm = bvec;
        const float* ad = adg + (size_t)b * 16;
        #pragma unroll
        for (int a = 0; a < 16; a++) qm = fmaf(-Lgs[w][m * 16 + a], ad[a], qm);
        g_q[(size_t)b * 8 + m] = qm;
    }

    // S = 0.5 Lg Lg^T
    #pragma unroll
    for (int e = 0; e < 2; e++) {
        int idx = lane + e * 32;
        int r = idx >> 3, cI = idx & 7;
        float s = 0.f;
        #pragma unroll
        for (int a = 0; a < 16; a++) s = fmaf(Lgs[w][r * 16 + a], Lgs[w][cI * 16 + a], s);
        g_S[(size_t)b * 64 + idx] = 0.5f * s;
    }
}

// =====================================================================
// Kernel 3: thread per element.  Packed power iteration + packed FISTA.
// =====================================================================
__global__ __launch_bounds__(128) void k3_fista(const float* __restrict__ adg,
                                                float* __restrict__ out, int batch)
{
    int b = blockIdx.x * 128 + threadIdx.x;
    if (b >= batch) return;

    ull Sp[32];   // 8 rows x 4 packed pairs
    {
        const ulonglong2* S2 = (const ulonglong2*)(g_S + (size_t)b * 64);
        #pragma unroll
        for (int i = 0; i < 16; i++) {
            ulonglong2 v = S2[i];
            Sp[2 * i] = v.x; Sp[2 * i + 1] = v.y;
        }
    }
    float q[8];
    {
        const float4* q4 = (const float4*)(g_q + (size_t)b * 8);
        float4 a0 = q4[0], a1 = q4[1];
        q[0] = a0.x; q[1] = a0.y; q[2] = a0.z; q[3] = a0.w;
        q[4] = a1.x; q[5] = a1.y; q[6] = a1.z; q[7] = a1.w;
    }

    // ---- power iteration on S (8x8) ----
    float v[8];
    #pragma unroll
    for (int k = 0; k < 8; k++) v[k] = 1.0f + 0.0625f * (float)k;
    #pragma unroll 1
    for (int it = 0; it < POW_ITERS; it++) {
        ull vp[4];
        #pragma unroll
        for (int j = 0; j < 4; j++) vp[j] = pack2(v[2 * j], v[2 * j + 1]);
        float wv[8];
        #pragma unroll
        for (int k = 0; k < 8; k++) wv[k] = dot8p(Sp + 4 * k, vp);
        float ss = 1e-30f;
        #pragma unroll
        for (int k = 0; k < 8; k++) ss = fmaf(wv[k], wv[k], ss);
        float inv = rsqrtf(ss);
        #pragma unroll
        for (int k = 0; k < 8; k++) v[k] = wv[k] * inv;
    }
    float num = 0.f, den = 1e-30f;
    {
        ull vp[4];
        #pragma unroll
        for (int j = 0; j < 4; j++) vp[j] = pack2(v[2 * j], v[2 * j + 1]);
        #pragma unroll
        for (int k = 0; k < 8; k++) {
            num = fmaf(v[k], dot8p(Sp + 4 * k, vp), num);
            den = fmaf(v[k], v[k], den);
        }
    }
    float mu = fmaxf(num / den, 0.f);
    float lamMax = EPSC + 0.5f * (mu + sqrtf(fmaf(mu, mu, 4.f * EPSC * EPSC)));
    float L = lamMax * 1.005f + 1e-6f;
    float t = 1.0f / L;

    // ---- FISTA (140 iters; both trajectories converged well before) ----
    float lam[16], y[16];
    #pragma unroll
    for (int k = 0; k < 16; k++) { lam[k] = 0.f; y[k] = 0.f; }
    float tk = 1.0f;
    #pragma unroll 1
    for (int it = 0; it < N_ITERS; it++) {
        ull yp[4];
        #pragma unroll
        for (int j = 0; j < 4; j++) yp[j] = pack2(y[2 * j], y[2 * j + 1]);
        float wv[8];
        #pragma unroll
        for (int k = 0; k < 8; k++) wv[k] = dot8p(Sp + 4 * k, yp);
        float tk1 = 0.5f * (1.0f + sqrtf(fmaf(4.0f * tk, tk, 1.0f)));
        float beta = (tk - 1.0f) / tk1;
        #pragma unroll
        for (int k = 0; k < 8; k++) {
            float e  = EPSC * (y[k] + y[k + 8]);
            float gt = wv[k] + e - q[k];
            float lt = fmaxf(fmaf(-t, gt, y[k]), 0.f);
            float lb = fmaxf(fmaf(-t, e, y[k + 8]), 0.f);
            y[k]     = fmaf(beta, lt - lam[k], lt);
            y[k + 8] = fmaf(beta, lb - lam[k + 8], lb);
            lam[k] = lt; lam[k + 8] = lb;
        }
        tk = tk1;
    }

    // ---- primal recovery: a = a_des + 0.5 Lg^T lam_top ----
    float a[16];
    {
        const float4* ad4 = (const float4*)(adg + (size_t)b * 16);
        #pragma unroll
        for (int i = 0; i < 4; i++) {
            float4 t4 = ad4[i];
            a[i * 4 + 0] = t4.x; a[i * 4 + 1] = t4.y; a[i * 4 + 2] = t4.z; a[i * 4 + 3] = t4.w;
        }
        const float* Lgb = g_Lg + (size_t)b * 128;
        #pragma unroll
        for (int m = 0; m < 8; m++) {
            float lm = 0.5f * lam[m];
            #pragma unroll
            for (int j = 0; j < 16; j++) a[j] = fmaf(lm, Lgb[m * 16 + j], a[j]);
        }
    }
    float4* o4 = (float4*)(out + (size_t)b * 16);
    #pragma unroll
    for (int i = 0; i < 4; i++)
        o4[i] = make_float4(a[i * 4 + 0], a[i * 4 + 1], a[i * 4 + 2], a[i * 4 + 3]);
}

// =====================================================================
extern "C" void kernel_launch(void* const* d_in, const int* in_sizes, int n_in,
                              void* d_out, int out_size)
{
    const float* a_des = (const float*)d_in[0];
    const float* x     = (const float*)d_in[1];
    const float* A     = (const float*)d_in[2];
    const float* B     = (const float*)d_in[3];
    const float* Qc    = (const float*)d_in[4];
    const float* cc    = (const float*)d_in[5];
    const float* dc    = (const float*)d_in[6];
    const int batch = in_sizes[0] / ADIM;   // 16384

    cudaFuncSetAttribute(k1_gemm, cudaFuncAttributeMaxDynamicSharedMemorySize, K1_SMEM);

    dim3 g1(batch / 128, 512 / 64);
    k1_gemm<<<g1, 128, K1_SMEM>>>(x, Qc);
    k2_setup<<<batch / 4, 128>>>(x, A, B, cc, dc, a_des);
    k3_fista<<<(batch + 127) / 128, 128>>>(a_des, (float*)d_out, batch);
}

// round 6
// speedup vs baseline: 1.6809x; 1.0235x over previous
#include <cuda_runtime.h>
#include <cstdint>

#define BATCH_MAX 16384
#define XDIM 64
#define ADIM 16
#define NCON 8
#define N_ITERS 140
#define POW_ITERS 32
#define EPSC 0.05f   /* 1/(2*PEN) */

typedef unsigned long long ull;

// ---------------- packed f32x2 helpers (sm_103a FFMA2) ----------------
__device__ __forceinline__ ull ffma2(ull a, ull b, ull c) {
    ull d;
    asm("fma.rn.f32x2 %0, %1, %2, %3;" : "=l"(d) : "l"(a), "l"(b), "l"(c));
    return d;
}
__device__ __forceinline__ float hadd2(ull p) {
    unsigned lo, hi;
    asm("mov.b64 {%0, %1}, %2;" : "=r"(lo), "=r"(hi) : "l"(p));
    return __uint_as_float(lo) + __uint_as_float(hi);
}
__device__ __forceinline__ ull pack2(float a, float b) {
    ull d;
    asm("mov.b64 %0, {%1, %2};" : "=l"(d)
        : "r"(__float_as_uint(a)), "r"(__float_as_uint(b)));
    return d;
}
__device__ __forceinline__ float dot8p(const ull* Sr, const ull* yp) {
    ull acc = ffma2(Sr[0], yp[0], 0ULL);
    acc = ffma2(Sr[1], yp[1], acc);
    acc = ffma2(Sr[2], yp[2], acc);
    acc = ffma2(Sr[3], yp[3], acc);
    return hadd2(acc);
}

// ---------------- cp.async helpers ----------------
__device__ __forceinline__ void cp_async16(void* smem_ptr, const void* gptr) {
    uint32_t a = (uint32_t)__cvta_generic_to_shared(smem_ptr);
    asm volatile("cp.async.cg.shared.global [%0], [%1], 16;" :: "r"(a), "l"(gptr));
}
#define CP_COMMIT() asm volatile("cp.async.commit_group;")
#define CP_WAIT(n)  asm volatile("cp.async.wait_group %0;" :: "n"(n))

// ---------------- scratch (static device globals; no runtime alloc) ----------------
__device__ float g_Y [BATCH_MAX * 512];   // Qc_m x  (flattened r = m*64+i)
__device__ float g_S [BATCH_MAX * 64];    // S = 0.5 Lg Lg^T  (8x8)
__device__ float g_q [BATCH_MAX * 8];     // dual linear term (top half; bottom == 0)
__device__ float g_Lg[BATCH_MAX * 128];   // Lg_h (8x16)

// =====================================================================
// Kernel 1: unchanged from R5 (43us; parked).
// =====================================================================
#define K1_XS_BYTES  (16 * 129 * 16)
#define K1_WK_BYTES  (64 * 64 * 4)
#define K1_BUF_BYTES (32 * 129 * 4)
#define K1_SMEM (K1_XS_BYTES + K1_WK_BYTES + K1_BUF_BYTES)

__global__ __launch_bounds__(128) void k1_gemm(const float* __restrict__ X,
                                               const float* __restrict__ W)
{
    extern __shared__ char sm_raw[];
    float4 (*Xs4)[129] = (float4(*)[129])sm_raw;
    float  (*Wk)[64]   = (float(*)[64])(sm_raw + K1_XS_BYTES);
    float  (*buf)[129] = (float(*)[129])(sm_raw + K1_XS_BYTES + K1_WK_BYTES);

    const int t  = threadIdx.x;
    const int m0 = blockIdx.x * 128;
    const int n0 = blockIdx.y * 64;
    const int kq = t & 15, rg = t >> 4;

    const float4* X4 = (const float4*)X;
    const float4* W4 = (const float4*)W;
    #pragma unroll
    for (int it = 0; it < 16; it++) {
        int row = it * 8 + rg;
        Xs4[kq][row] = X4[(size_t)(m0 + row) * 16 + kq];
    }
    #pragma unroll
    for (int it = 0; it < 8; it++) {
        int n = it * 8 + rg;
        *(float4*)&Wk[n][kq * 4] = W4[(size_t)(n0 + n) * 16 + kq];
    }
    __syncthreads();

    const int lane = t & 31, w = t >> 5;
    const int m = w * 32 + lane;

    #pragma unroll 1
    for (int pass = 0; pass < 2; pass++) {
        ull acc2[32];
        #pragma unroll
        for (int n = 0; n < 32; n++) acc2[n] = 0ULL;

        const float (*Wp)[64] = Wk + pass * 32;
        #pragma unroll 4
        for (int kq2 = 0; kq2 < 16; kq2++) {
            ulonglong2 xq = *(const ulonglong2*)&Xs4[kq2][m];
            #pragma unroll
            for (int n = 0; n < 32; n++) {
                ulonglong2 wq = *(const ulonglong2*)&Wp[n][kq2 * 4];
                acc2[n] = ffma2(wq.x, xq.x, acc2[n]);
                acc2[n] = ffma2(wq.y, xq.y, acc2[n]);
            }
        }

        #pragma unroll
        for (int n = 0; n < 32; n++) buf[n][m] = hadd2(acc2[n]);
        __syncthreads();
        {
            int n4 = t & 7, mg = t >> 3;
            #pragma unroll
            for (int s = 0; s < 8; s++) {
                int mr = s * 16 + mg;
                float4 o = make_float4(buf[n4 * 4 + 0][mr], buf[n4 * 4 + 1][mr],
                                       buf[n4 * 4 + 2][mr], buf[n4 * 4 + 3][mr]);
                ((float4*)g_Y)[(size_t)(m0 + mr) * 128 + n0 / 4 + pass * 8 + n4] = o;
            }
        }
        __syncthreads();
    }
}

// =====================================================================
// Kernel 2: per-element setup.  cp.async depth-2 pipeline for z=Ax;
// B tile cp.async'd into the retired A-stage buffer (smem union).
// =====================================================================
#define GS_STRIDE 68

__global__ __launch_bounds__(128) void k2_setup(
    const float* __restrict__ Xg, const float* __restrict__ Ag,
    const float* __restrict__ Bg, const float* __restrict__ ccg,
    const float* __restrict__ dcg, const float* __restrict__ adg)
{
    __shared__ float xs [4][64];
    __shared__ float zs [4][64];
    __shared__ float gsm[4][NCON * GS_STRIDE];  // gradc
    __shared__ float stg[4][2 * 544];           // A double-stage; later B[64][16]
    __shared__ float Lgs[4][128];
    __shared__ float ccs[512];

    const int tid = threadIdx.x;
    const int w = tid >> 5, lane = tid & 31;
    const int b = blockIdx.x * 4 + w;

    for (int idx = tid; idx < 512; idx += 128) ccs[idx] = ccg[idx];

    if (lane < 16)
        *(float4*)&xs[w][lane * 4] = *(const float4*)(Xg + (size_t)b * 64 + lane * 4);

    const float4* A4 = (const float4*)(Ag + (size_t)b * 4096);

    // ---- prologue: chunks 0,1 in flight ----
    #pragma unroll
    for (int c = 0; c < 2; c++) {
        #pragma unroll
        for (int j = 0; j < 4; j++) {
            int p = j * 32 + lane;
            cp_async16(&stg[w][c * 544 + (p >> 4) * GS_STRIDE + (p & 15) * 4],
                       A4 + c * 128 + p);
        }
        CP_COMMIT();
    }
    __syncthreads();   // xs/ccs visible

    // ---- z = A x, software-pipelined ----
    {
        const int r = lane & 7, seg = lane >> 3;
        #pragma unroll
        for (int ch = 0; ch < 8; ch++) {
            if (ch < 7) { CP_WAIT(1); } else { CP_WAIT(0); }
            __syncwarp();
            const float* st = &stg[w][(ch & 1) * 544];
            float acc = 0.f;
            #pragma unroll
            for (int j = 0; j < 4; j++) {
                float4 av = *(const float4*)&st[r * GS_STRIDE + seg * 16 + j * 4];
                float4 xv = *(const float4*)&xs[w][seg * 16 + j * 4];
                acc = fmaf(av.x, xv.x, acc);
                acc = fmaf(av.y, xv.y, acc);
                acc = fmaf(av.z, xv.z, acc);
                acc = fmaf(av.w, xv.w, acc);
            }
            acc += __shfl_xor_sync(0xffffffffu, acc, 8);
            acc += __shfl_xor_sync(0xffffffffu, acc, 16);
            if (seg == 0) zs[w][ch * 8 + r] = acc;
            __syncwarp();   // reads done before refilling this stage
            if (ch + 2 < 8) {
                #pragma unroll
                for (int j = 0; j < 4; j++) {
                    int p = j * 32 + lane;
                    cp_async16(&stg[w][(ch & 1) * 544 + (p >> 4) * GS_STRIDE + (p & 15) * 4],
                               A4 + (ch + 2) * 128 + p);
                }
                CP_COMMIT();
            }
        }
    }

    // ---- B tile -> stg[w][0..1023] (A stage fully retired) ----
    {
        const float* Bb = Bg + (size_t)b * 1024;
        #pragma unroll
        for (int it = 0; it < 8; it++) {
            int idx = it * 128 + lane * 4;
            cp_async16(&stg[w][idx], Bb + idx);
        }
        CP_COMMIT();
    }

    // ---- gradc = Y + cc (overlaps with B cp.async) ----
    {
        const float* Yb = g_Y + (size_t)b * 512;
        #pragma unroll
        for (int it = 0; it < 4; it++) {
            int idx = it * 128 + lane * 4;
            int m = idx >> 6, i = idx & 63;
            float4 yv = *(const float4*)(Yb + idx);
            yv.x += ccs[idx + 0]; yv.y += ccs[idx + 1];
            yv.z += ccs[idx + 2]; yv.w += ccs[idx + 3];
            *(float4*)&gsm[w][m * GS_STRIDE + i] = yv;
        }
    }
    __syncwarp();

    // dots: sa = x·gradc, sb = x·cc, sc = z·gradc
    float sa[NCON], sb[NCON], sc[NCON];
    {
        int i1 = lane, i2 = lane + 32;
        float x1 = xs[w][i1], x2 = xs[w][i2];
        float z1 = zs[w][i1], z2 = zs[w][i2];
        #pragma unroll
        for (int m = 0; m < NCON; m++) {
            float ga = gsm[w][m * GS_STRIDE + i1], gb2 = gsm[w][m * GS_STRIDE + i2];
            float ca = ccs[m * 64 + i1], cb = ccs[m * 64 + i2];
            sa[m] = fmaf(x2, gb2, x1 * ga);
            sb[m] = fmaf(x2, cb, x1 * ca);
            sc[m] = fmaf(z2, gb2, z1 * ga);
        }
    }
    #pragma unroll
    for (int off = 16; off; off >>= 1) {
        #pragma unroll
        for (int m = 0; m < NCON; m++) {
            sa[m] += __shfl_xor_sync(0xffffffffu, sa[m], off);
            sb[m] += __shfl_xor_sync(0xffffffffu, sb[m], off);
            sc[m] += __shfl_xor_sync(0xffffffffu, sc[m], off);
        }
    }

    CP_WAIT(0);
    __syncwarp();   // B tile resident

    // Lg[m][a] = -sum_i gradc[m][i] * B[i][a]
    {
        int m = lane >> 2, aq = lane & 3;
        float4 acc = make_float4(0.f, 0.f, 0.f, 0.f);
        const float4* B4 = (const float4*)&stg[w][0];
        #pragma unroll
        for (int i = 0; i < 64; i++) {
            float gv = gsm[w][m * GS_STRIDE + i];
            float4 bv = B4[i * 4 + aq];
            acc.x = fmaf(gv, bv.x, acc.x);
            acc.y = fmaf(gv, bv.y, acc.y);
            acc.z = fmaf(gv, bv.z, acc.z);
            acc.w = fmaf(gv, bv.w, acc.w);
        }
        acc.x = -acc.x; acc.y = -acc.y; acc.z = -acc.z; acc.w = -acc.w;
        *(float4*)&Lgs[w][m * 16 + aq * 4] = acc;
        *(float4*)(g_Lg + (size_t)b * 128 + m * 16 + aq * 4) = acc;
    }
    __syncwarp();

    // q top = bvec - Lg a_des
    if (lane < NCON) {
        int m = lane;
        float g    = 0.5f * sa[m] + 0.5f * sb[m] - dcg[m];
        float bvec = sc[m] + g;
        float qm = bvec;
        const float* ad = adg + (size_t)b * 16;
        #pragma unroll
        for (int a = 0; a < 16; a++) qm = fmaf(-Lgs[w][m * 16 + a], ad[a], qm);
        g_q[(size_t)b * 8 + m] = qm;
    }

    // S = 0.5 Lg Lg^T
    #pragma unroll
    for (int e = 0; e < 2; e++) {
        int idx = lane + e * 32;
        int r = idx >> 3, cI = idx & 7;
        float s = 0.f;
        #pragma unroll
        for (int a = 0; a < 16; a++) s = fmaf(Lgs[w][r * 16 + a], Lgs[w][cI * 16 + a], s);
        g_S[(size_t)b * 64 + idx] = 0.5f * s;
    }
}

// =====================================================================
// Kernel 3: unchanged from R5 (frozen for attribution).
// =====================================================================
__global__ __launch_bounds__(128) void k3_fista(const float* __restrict__ adg,
                                                float* __restrict__ out, int batch)
{
    int b = blockIdx.x * 128 + threadIdx.x;
    if (b >= batch) return;

    ull Sp[32];
    {
        const ulonglong2* S2 = (const ulonglong2*)(g_S + (size_t)b * 64);
        #pragma unroll
        for (int i = 0; i < 16; i++) {
            ulonglong2 v = S2[i];
            Sp[2 * i] = v.x; Sp[2 * i + 1] = v.y;
        }
    }
    float q[8];
    {
        const float4* q4 = (const float4*)(g_q + (size_t)b * 8);
        float4 a0 = q4[0], a1 = q4[1];
        q[0] = a0.x; q[1] = a0.y; q[2] = a0.z; q[3] = a0.w;
        q[4] = a1.x; q[5] = a1.y; q[6] = a1.z; q[7] = a1.w;
    }

    float v[8];
    #pragma unroll
    for (int k = 0; k < 8; k++) v[k] = 1.0f + 0.0625f * (float)k;
    #pragma unroll 1
    for (int it = 0; it < POW_ITERS; it++) {
        ull vp[4];
        #pragma unroll
        for (int j = 0; j < 4; j++) vp[j] = pack2(v[2 * j], v[2 * j + 1]);
        float wv[8];
        #pragma unroll
        for (int k = 0; k < 8; k++) wv[k] = dot8p(Sp + 4 * k, vp);
        float ss = 1e-30f;
        #pragma unroll
        for (int k = 0; k < 8; k++) ss = fmaf(wv[k], wv[k], ss);
        float inv = rsqrtf(ss);
        #pragma unroll
        for (int k = 0; k < 8; k++) v[k] = wv[k] * inv;
    }
    float num = 0.f, den = 1e-30f;
    {
        ull vp[4];
        #pragma unroll
        for (int j = 0; j < 4; j++) vp[j] = pack2(v[2 * j], v[2 * j + 1]);
        #pragma unroll
        for (int k = 0; k < 8; k++) {
            num = fmaf(v[k], dot8p(Sp + 4 * k, vp), num);
            den = fmaf(v[k], v[k], den);
        }
    }
    float mu = fmaxf(num / den, 0.f);
    float lamMax = EPSC + 0.5f * (mu + sqrtf(fmaf(mu, mu, 4.f * EPSC * EPSC)));
    float L = lamMax * 1.005f + 1e-6f;
    float t = 1.0f / L;

    float lam[16], y[16];
    #pragma unroll
    for (int k = 0; k < 16; k++) { lam[k] = 0.f; y[k] = 0.f; }
    float tk = 1.0f;
    #pragma unroll 1
    for (int it = 0; it < N_ITERS; it++) {
        ull yp[4];
        #pragma unroll
        for (int j = 0; j < 4; j++) yp[j] = pack2(y[2 * j], y[2 * j + 1]);
        float wv[8];
        #pragma unroll
        for (int k = 0; k < 8; k++) wv[k] = dot8p(Sp + 4 * k, yp);
        float tk1 = 0.5f * (1.0f + sqrtf(fmaf(4.0f * tk, tk, 1.0f)));
        float beta = (tk - 1.0f) / tk1;
        #pragma unroll
        for (int k = 0; k < 8; k++) {
            float e  = EPSC * (y[k] + y[k + 8]);
            float gt = wv[k] + e - q[k];
            float lt = fmaxf(fmaf(-t, gt, y[k]), 0.f);
            float lb = fmaxf(fmaf(-t, e, y[k + 8]), 0.f);
            y[k]     = fmaf(beta, lt - lam[k], lt);
            y[k + 8] = fmaf(beta, lb - lam[k + 8], lb);
            lam[k] = lt; lam[k + 8] = lb;
        }
        tk = tk1;
    }

    float a[16];
    {
        const float4* ad4 = (const float4*)(adg + (size_t)b * 16);
        #pragma unroll
        for (int i = 0; i < 4; i++) {
            float4 t4 = ad4[i];
            a[i * 4 + 0] = t4.x; a[i * 4 + 1] = t4.y; a[i * 4 + 2] = t4.z; a[i * 4 + 3] = t4.w;
        }
        const float* Lgb = g_Lg + (size_t)b * 128;
        #pragma unroll
        for (int m = 0; m < 8; m++) {
            float lm = 0.5f * lam[m];
            #pragma unroll
            for (int j = 0; j < 16; j++) a[j] = fmaf(lm, Lgb[m * 16 + j], a[j]);
        }
    }
    float4* o4 = (float4*)(out + (size_t)b * 16);
    #pragma unroll
    for (int i = 0; i < 4; i++)
        o4[i] = make_float4(a[i * 4 + 0], a[i * 4 + 1], a[i * 4 + 2], a[i * 4 + 3]);
}

// =====================================================================
extern "C" void kernel_launch(void* const* d_in, const int* in_sizes, int n_in,
                              void* d_out, int out_size)
{
    const float* a_des = (const float*)d_in[0];
    const float* x     = (const float*)d_in[1];
    const float* A     = (const float*)d_in[2];
    const float* B     = (const float*)d_in[3];
    const float* Qc    = (const float*)d_in[4];
    const float* cc    = (const float*)d_in[5];
    const float* dc    = (const float*)d_in[6];
    const int batch = in_sizes[0] / ADIM;   // 16384

    cudaFuncSetAttribute(k1_gemm, cudaFuncAttributeMaxDynamicSharedMemorySize, K1_SMEM);

    dim3 g1(batch / 128, 512 / 64);
    k1_gemm<<<g1, 128, K1_SMEM>>>(x, Qc);
    k2_setup<<<batch / 4, 128>>>(x, A, B, cc, dc, a_des);
    k3_fista<<<(batch + 127) / 128, 128>>>(a_des, (float*)d_out, batch);
}